// round 14
// baseline (speedup 1.0000x reference)
#include <cuda_runtime.h>
#include <cuda_bf16.h>
#include <math.h>

// ---------------- problem constants ----------------
#define B_   32
#define S_   128
#define E_   300
#define C_   100
#define EC_  50
#define LC_  50
#define H_   256
#define L_   17
#define G4_  1024          // 4*H
#define D_   400           // E + C

typedef unsigned long long u64;

// ---------------- scratch ----------------
__device__ float g_conv1[B_ * C_ * 48];
__device__ float g_conv2[B_ * C_ * 45];
__device__ float g_pooled[B_ * C_];
__device__ float g_gin[2 * S_ * G4_ * B_];              // preactivations [dir][s][r][b]  (TRANSPOSED)
__device__ float g_hseq[2 * S_ * B_ * H_];              // LSTM outputs [dir][s][b][256]
__device__ float g_em[B_ * L_ * S_];                    // emissions [b][l][s]
__device__ __align__(256) unsigned int g_slots[128];    // per-block step slots [dir*64+blk]

__device__ __forceinline__ float sigm(float x) { return 1.f / (1.f + expf(-x)); }

// packed f32x2 fma: acc += a*b (elementwise on 2 floats)
__device__ __forceinline__ void ffma2(u64 &acc, u64 a, u64 b) {
    asm("fma.rn.f32x2 %0, %1, %2, %0;" : "+l"(acc) : "l"(a), "l"(b));
}
// 128-bit shared load as two u64 (two f32x2 pairs)
__device__ __forceinline__ void lds_v2u64(u64 &a, u64 &b, const void* p) {
    unsigned sa = (unsigned)__cvta_generic_to_shared(p);
    asm volatile("ld.shared.v2.b64 {%0, %1}, [%2];" : "=l"(a), "=l"(b) : "r"(sa));
}
__device__ __forceinline__ float f2sum(u64 v) {
    float lo, hi;
    asm("mov.b64 {%0, %1}, %2;" : "=f"(lo), "=f"(hi) : "l"(v));
    return lo + hi;
}

// ---------------- char CNN ----------------
__global__ void __launch_bounds__(128) conv1_kernel(const int* __restrict__ xc,
                                                    const float* __restrict__ cemb,
                                                    const float* __restrict__ w1,
                                                    const float* __restrict__ b1) {
    int b = blockIdx.x;
    int oc0 = blockIdx.y * 25;
    __shared__ float ce[EC_][LC_];
    int tid = threadIdx.x;
    for (int i = tid; i < EC_ * LC_; i += 128) {
        int e = i / LC_, t = i % LC_;
        ce[e][t] = cemb[xc[b * LC_ + t] * EC_ + e];
    }
    __syncthreads();
    for (int i = tid; i < 25 * 48; i += 128) {
        int o = i / 48, t = i % 48;
        const float* wr = w1 + (size_t)(oc0 + o) * (EC_ * 3);
        float acc = b1[oc0 + o];
        for (int e = 0; e < EC_; e++) {
            acc += ce[e][t + 0] * wr[e * 3 + 0];
            acc += ce[e][t + 1] * wr[e * 3 + 1];
            acc += ce[e][t + 2] * wr[e * 3 + 2];
        }
        g_conv1[b * (C_ * 48) + (oc0 + o) * 48 + t] = fmaxf(acc, 0.f);
    }
}

__global__ void __launch_bounds__(128) conv2_kernel(const float* __restrict__ w2,
                                                    const float* __restrict__ b2) {
    int b = blockIdx.x;
    int oc0 = blockIdx.y * 25;
    __shared__ float in_s[C_][48];
    int tid = threadIdx.x;
    for (int i = tid; i < C_ * 48; i += 128) ((float*)in_s)[i] = g_conv1[b * (C_ * 48) + i];
    __syncthreads();
    for (int i = tid; i < 25 * 45; i += 128) {
        int o = i / 45, t = i % 45;
        const float* wr = w2 + (size_t)(oc0 + o) * (C_ * 4);
        float acc = b2[oc0 + o];
        for (int ic = 0; ic < C_; ic++) {
            acc += in_s[ic][t + 0] * wr[ic * 4 + 0];
            acc += in_s[ic][t + 1] * wr[ic * 4 + 1];
            acc += in_s[ic][t + 2] * wr[ic * 4 + 2];
            acc += in_s[ic][t + 3] * wr[ic * 4 + 3];
        }
        g_conv2[b * (C_ * 45) + (oc0 + o) * 45 + t] = fmaxf(acc, 0.f);
    }
}

__global__ void __launch_bounds__(128) conv3_kernel(const float* __restrict__ w3,
                                                    const float* __restrict__ b3) {
    int b = blockIdx.x;
    int oc0 = blockIdx.y * 25;
    __shared__ float in_s[C_][45];
    __shared__ float out_s[25][41];
    int tid = threadIdx.x;
    for (int i = tid; i < C_ * 45; i += 128) ((float*)in_s)[i] = g_conv2[b * (C_ * 45) + i];
    __syncthreads();
    for (int i = tid; i < 25 * 41; i += 128) {
        int o = i / 41, t = i % 41;
        const float* wr = w3 + (size_t)(oc0 + o) * (C_ * 5);
        float acc = b3[oc0 + o];
        for (int ic = 0; ic < C_; ic++) {
            acc += in_s[ic][t + 0] * wr[ic * 5 + 0];
            acc += in_s[ic][t + 1] * wr[ic * 5 + 1];
            acc += in_s[ic][t + 2] * wr[ic * 5 + 2];
            acc += in_s[ic][t + 3] * wr[ic * 5 + 3];
            acc += in_s[ic][t + 4] * wr[ic * 5 + 4];
        }
        out_s[o][t] = fmaxf(acc, 0.f);
    }
    __syncthreads();
    if (tid < 25) {
        float m = out_s[tid][0];
        for (int t = 1; t < 41; t++) m = fmaxf(m, out_s[tid][t]);
        g_pooled[b * C_ + oc0 + tid] = m;
    }
}

// ---------------- input GEMM (K=400), single-buffered (best measured) ----------------
__global__ void __launch_bounds__(256) gemm_input_kernel(const int* __restrict__ x,
                                                         const float* __restrict__ word_emb,
                                                         const float* __restrict__ w_ih_f,
                                                         const float* __restrict__ w_ih_b,
                                                         const float* __restrict__ b_f,
                                                         const float* __restrict__ b_b) {
    const int dir = blockIdx.z;
    const float* __restrict__ W = dir ? w_ih_b : w_ih_f;
    const float* __restrict__ bias = dir ? b_b : b_f;
    float* __restrict__ out = g_gin + (size_t)dir * (S_ * G4_ * B_);
    const int m0 = blockIdx.y * 128;
    const int n0 = blockIdx.x * 128;
    __shared__ float As[16][132];
    __shared__ float Bs[16][132];
    __shared__ int wid[128];
    __shared__ float bsh[128];
    const int tid = threadIdx.x;
    if (tid < 128) {
        int m = m0 + tid;
        wid[tid] = x[(m & 31) * S_ + (m >> 5)];   // b = m&31, s = m>>5
        bsh[tid] = bias[n0 + tid];
    }
    __syncthreads();
    const int tx = tid & 15, ty = tid >> 4;
    float acc[8][8];
    #pragma unroll
    for (int i = 0; i < 8; i++)
        #pragma unroll
        for (int j = 0; j < 8; j++) acc[i][j] = 0.f;

    for (int k0 = 0; k0 < 400; k0 += 16) {
        #pragma unroll
        for (int l = 0; l < 2; l++) {
            int idx = tid + l * 256;
            int row = idx >> 2;
            int kq = (idx & 3) * 4;
            int k = k0 + kq;
            float4 av;
            if (k < 300) {
                av = *reinterpret_cast<const float4*>(word_emb + (size_t)wid[row] * E_ + k);
            } else {
                int bb = (m0 + row) & 31;
                av = *reinterpret_cast<const float4*>(g_pooled + bb * C_ + (k - 300));
            }
            As[kq + 0][row] = av.x;
            As[kq + 1][row] = av.y;
            As[kq + 2][row] = av.z;
            As[kq + 3][row] = av.w;
            float4 bv = *reinterpret_cast<const float4*>(W + (size_t)(n0 + row) * D_ + k);
            Bs[kq + 0][row] = bv.x;
            Bs[kq + 1][row] = bv.y;
            Bs[kq + 2][row] = bv.z;
            Bs[kq + 3][row] = bv.w;
        }
        __syncthreads();
        #pragma unroll
        for (int kk = 0; kk < 16; kk++) {
            float a[8], bq[8];
            #pragma unroll
            for (int i = 0; i < 8; i++) a[i] = As[kk][ty * 8 + i];
            #pragma unroll
            for (int j = 0; j < 8; j++) bq[j] = Bs[kk][tx * 8 + j];
            #pragma unroll
            for (int i = 0; i < 8; i++)
                #pragma unroll
                for (int j = 0; j < 8; j++) acc[i][j] += a[i] * bq[j];
        }
        __syncthreads();
    }
    #pragma unroll
    for (int i = 0; i < 8; i++) {
        int m = m0 + ty * 8 + i;
        int s = m >> 5;
        int bb = m & 31;
        float* obase = out + (size_t)s * (G4_ * B_) + bb;
        #pragma unroll
        for (int j = 0; j < 8; j++) {
            int n = n0 + tx * 8 + j;
            obase[(size_t)n * B_] = acc[i][j] + bsh[tx * 8 + j];
        }
    }
}

// ---------------- persistent bidirectional LSTM ----------------
__global__ void __launch_bounds__(128) zero_bar_kernel() { g_slots[threadIdx.x] = 0u; }

// Atomic-free per-direction barrier:
//   arrival: st.release to the block's OWN slot (no RMW -> no LTS serialization)
//   detect : tid0 only, 16x ld.relaxed.v4 per round (MLP=16, ~1 L2 latency/round),
//            then fence.acq_rel (pairs with producers' release stores), syncthreads.
__device__ __forceinline__ void dir_barrier(int dir, int blk, int t) {
    __syncthreads();                      // all block stores done before signal
    const unsigned tgt = (unsigned)(t + 1);
    if (threadIdx.x == 0) {
        asm volatile("st.release.gpu.global.u32 [%0], %1;"
                     :: "l"(&g_slots[dir * 64 + blk]), "r"(tgt) : "memory");
        const unsigned int* base = &g_slots[dir * 64];
        bool ok;
        do {
            ok = true;
            #pragma unroll
            for (int i = 0; i < 16; i++) {
                unsigned a, b, c, d;
                asm volatile("ld.relaxed.gpu.global.v4.u32 {%0,%1,%2,%3}, [%4];"
                             : "=r"(a), "=r"(b), "=r"(c), "=r"(d)
                             : "l"(base + i * 4) : "memory");
                ok = ok && (a >= tgt) && (b >= tgt) && (c >= tgt) && (d >= tgt);
            }
        } while (!ok);
        asm volatile("fence.acq_rel.gpu;" ::: "memory");
    }
    __syncthreads();                      // publish tid0's acquire to the block
}

// 128 blocks (64/dir), 256 thr. Warp = K-eighth, covers ALL 16 gate rows.
__global__ void __launch_bounds__(256) lstm_persist_kernel(const float* __restrict__ w_hh_f,
                                                           const float* __restrict__ w_hh_b,
                                                           const float* __restrict__ h0,
                                                           const float* __restrict__ c0) {
    const int dir = blockIdx.x >> 6;
    const int blk = blockIdx.x & 63;
    const int j0 = blk * 4;                // 4 hidden units per block
    const float* __restrict__ W = dir ? w_hh_b : w_hh_f;
    __shared__ __align__(16) float wsh[16][256];   // [rr = gate*4+unit][k]
    __shared__ __align__(16) float hs[32][260];    // [b][k], +4 pad -> conflict-free LDS.128
    __shared__ float psh[8][16][33];               // K-eighth partials [kh][rr][b]
    __shared__ float csh[4][32];                   // cell state [u][b]
    const int tid = threadIdx.x;
    for (int i = tid; i < 16 * 256; i += 256) {
        int r = i >> 8, k = i & 255;
        int row = (r >> 2) * H_ + j0 + (r & 3);
        wsh[r][k] = W[(size_t)row * H_ + k];
    }
    if (tid < 128) {
        int u = tid >> 5, b = tid & 31;
        csh[u][b] = c0[dir * (B_ * H_) + b * H_ + j0 + u];
    }
    __syncthreads();

    float* __restrict__ hseq = g_hseq + (size_t)dir * (S_ * B_ * H_);
    const float* __restrict__ gin = g_gin + (size_t)dir * (S_ * G4_ * B_);
    const int wd = tid >> 5;               // warp 0..7 = K-eighth
    const int lane = tid & 31;             // batch
    const int kbase = wd * 32;             // 32 k per eighth (8 chunks of 4)
    const int cu = tid >> 5;               // combine role: unit (valid when tid<128)

    for (int t = 0; t < S_; t++) {
        const int s = dir ? (S_ - 1 - t) : t;
        const int sp = dir ? (s + 1) : (s - 1);
        const float* hprev = (t == 0) ? (h0 + dir * (B_ * H_))
                                      : (hseq + (size_t)sp * (B_ * H_));
        // prefetch gin for the combine stage (independent of h)
        const float* grow = gin + (size_t)s * (G4_ * B_);
        float gpre0 = 0.f, gpre1 = 0.f, gpre2 = 0.f, gpre3 = 0.f;
        if (tid < 128) {
            gpre0 = __ldg(&grow[(0 * H_ + j0 + cu) * B_ + lane]);
            gpre1 = __ldg(&grow[(1 * H_ + j0 + cu) * B_ + lane]);
            gpre2 = __ldg(&grow[(2 * H_ + j0 + cu) * B_ + lane]);
            gpre3 = __ldg(&grow[(3 * H_ + j0 + cu) * B_ + lane]);
        }
        // stage h -> smem (coherent: written by other blocks intra-kernel)
        const float4* hp4 = (const float4*)hprev;
        #pragma unroll
        for (int i = 0; i < 8; i++) {
            int idx = tid + i * 256;
            int b = idx >> 6, kq = idx & 63;
            float4 v = __ldcg(&hp4[idx]);
            *(float4*)&hs[b][kq * 4] = v;
        }
        __syncthreads();

        // all 16 rows x K-eighth partial dot; h loaded ONCE per chunk
        u64 acc[16];
        #pragma unroll
        for (int r = 0; r < 16; r++) acc[r] = 0;
        #pragma unroll
        for (int c = 0; c < 8; c++) {
            u64 h01, h23;
            lds_v2u64(h01, h23, &hs[lane][kbase + c * 4]);
            #pragma unroll
            for (int r = 0; r < 16; r++) {
                u64 w01, w23;
                lds_v2u64(w01, w23, &wsh[r][kbase + c * 4]);   // warp broadcast
                ffma2(acc[r], w01, h01);
                ffma2(acc[r], w23, h23);
            }
        }
        #pragma unroll
        for (int r = 0; r < 16; r++) psh[wd][r][lane] = f2sum(acc[r]);
        __syncthreads();

        if (tid < 128) {
            int u = cu, b = lane;
            float gi = gpre0, gf = gpre1, gg = gpre2, go = gpre3;
            #pragma unroll
            for (int kh = 0; kh < 8; kh++) {
                gi += psh[kh][0 * 4 + u][b];
                gf += psh[kh][1 * 4 + u][b];
                gg += psh[kh][2 * 4 + u][b];
                go += psh[kh][3 * 4 + u][b];
            }
            float c = sigm(gf) * csh[u][b] + sigm(gi) * tanhf(gg);
            csh[u][b] = c;
            __stcg(&hseq[(size_t)s * (B_ * H_) + b * H_ + j0 + u], sigm(go) * tanhf(c));
        }
        dir_barrier(dir, blk, t);
    }
}

// ---------------- fc -> emission logits (layout [b][l][s]) ----------------
__global__ void __launch_bounds__(256) fc_kernel(const float* __restrict__ fc_w,
                                                 const float* __restrict__ fc_b) {
    const int s = blockIdx.x;
    __shared__ float ws[L_ * 512];
    const int tid = threadIdx.x;
    for (int i = tid; i < L_ * 512; i += 256) ws[i] = fc_w[i];
    __syncthreads();
    const float* hf = g_hseq + (size_t)s * (B_ * H_);
    const float* hb = g_hseq + (size_t)(S_ * B_ * H_) + (size_t)s * (B_ * H_);
    for (int idx = tid; idx < B_ * L_; idx += 256) {
        int b = idx / L_, l = idx % L_;
        const float4* hf4 = (const float4*)(hf + b * H_);
        const float4* hb4 = (const float4*)(hb + b * H_);
        const float4* w0 = (const float4*)(ws + l * 512);
        const float4* w1 = w0 + 64;
        float acc = fc_b[l];
        #pragma unroll 8
        for (int k = 0; k < 64; k++) {
            float4 h4 = hf4[k], w4 = w0[k];
            acc += h4.x * w4.x + h4.y * w4.y + h4.z * w4.z + h4.w * w4.w;
            float4 h5 = hb4[k], w5 = w1[k];
            acc += h5.x * w5.x + h5.y * w5.y + h5.z * w5.z + h5.w * w5.w;
        }
        g_em[b * (L_ * S_) + l * S_ + s] = acc;
    }
}

// ---------------- softmax over seq dim ----------------
__global__ void __launch_bounds__(256) softmax_kernel() {
    int w = (blockIdx.x * 256 + threadIdx.x) >> 5;
    int lane = threadIdx.x & 31;
    if (w >= B_ * L_) return;
    float* row = g_em + (size_t)w * S_;
    float v[4];
    float mx = -1e30f;
    #pragma unroll
    for (int q = 0; q < 4; q++) { v[q] = row[lane + 32 * q]; mx = fmaxf(mx, v[q]); }
    #pragma unroll
    for (int o = 16; o; o >>= 1) mx = fmaxf(mx, __shfl_xor_sync(0xffffffffu, mx, o));
    float sum = 0.f;
    #pragma unroll
    for (int q = 0; q < 4; q++) { v[q] = expf(v[q] - mx); sum += v[q]; }
    #pragma unroll
    for (int o = 16; o; o >>= 1) sum += __shfl_xor_sync(0xffffffffu, sum, o);
    #pragma unroll
    for (int q = 0; q < 4; q++) row[lane + 32 * q] = v[q] / sum;
}

// ---------------- Viterbi: one warp-block per batch; float output ----------------
__global__ void __launch_bounds__(32) viterbi_kernel(const int* __restrict__ x,
                                                     const float* __restrict__ start_t,
                                                     const float* __restrict__ trans,
                                                     const float* __restrict__ end_t,
                                                     float* __restrict__ out) {
    const int b = blockIdx.x;
    const int j = threadIdx.x;
    __shared__ float esh[S_ * L_];         // [s][l]
    __shared__ float tsh[L_ * L_];
    __shared__ int hist[(S_ - 1) * L_];
    __shared__ unsigned char msk[S_];
    for (int i = j; i < S_ * L_; i += 32) {
        int l = i >> 7, s = i & 127;
        esh[s * L_ + l] = g_em[b * (L_ * S_) + i];
    }
    for (int i = j; i < L_ * L_; i += 32) tsh[i] = trans[i];
    for (int s = j; s < S_; s += 32) msk[s] = (x[b * S_ + s] != 0) ? 1 : 0;
    __syncthreads();
    const int jj = (j < L_) ? j : 0;
    float score = (j < L_) ? (start_t[j] + esh[jj]) : -1e30f;
    for (int s = 1; s < S_; s++) {
        float e = esh[s * L_ + jj];
        float best = -1e30f;
        int arg = 0;
        for (int i = 0; i < L_; i++) {
            float si = __shfl_sync(0xffffffffu, score, i);
            float v = si + tsh[i * L_ + jj];
            if (v > best) { best = v; arg = i; }
        }
        if (j < L_) {
            hist[(s - 1) * L_ + j] = arg;
            if (msk[s]) score = best + e;
        }
    }
    if (j < L_) score += end_t[j];
    float best = -1e30f;
    int last = 0;
    for (int i = 0; i < L_; i++) {
        float si = __shfl_sync(0xffffffffu, score, i);
        if (si > best) { best = si; last = i; }
    }
    if (j == 0) {
        int cur = last;
        out[b * S_ + S_ - 1] = (float)cur;
        for (int s = S_ - 2; s >= 0; s--) {
            if (msk[s + 1]) cur = hist[s * L_ + cur];
            out[b * S_ + s] = (float)cur;
        }
    }
}

// ---------------- launch ----------------
extern "C" void kernel_launch(void* const* d_in, const int* in_sizes, int n_in,
                              void* d_out, int out_size) {
    const int*   x        = (const int*)d_in[0];
    const int*   x_char   = (const int*)d_in[1];
    const float* word_emb = (const float*)d_in[2];
    const float* char_emb = (const float*)d_in[3];
    const float* conv1_w  = (const float*)d_in[4];
    const float* conv1_b  = (const float*)d_in[5];
    const float* conv2_w  = (const float*)d_in[6];
    const float* conv2_b  = (const float*)d_in[7];
    const float* conv3_w  = (const float*)d_in[8];
    const float* conv3_b  = (const float*)d_in[9];
    const float* w_ih_f   = (const float*)d_in[10];
    const float* w_hh_f   = (const float*)d_in[11];
    const float* b_f      = (const float*)d_in[12];
    const float* w_ih_b   = (const float*)d_in[13];
    const float* w_hh_b   = (const float*)d_in[14];
    const float* b_b      = (const float*)d_in[15];
    const float* h0       = (const float*)d_in[16];
    const float* c0       = (const float*)d_in[17];
    const float* fc_w     = (const float*)d_in[18];
    const float* fc_b     = (const float*)d_in[19];
    const float* start_t  = (const float*)d_in[20];
    const float* trans    = (const float*)d_in[21];
    const float* end_t    = (const float*)d_in[22];
    float* out = (float*)d_out;

    conv1_kernel<<<dim3(B_, 4), 128>>>(x_char, char_emb, conv1_w, conv1_b);
    conv2_kernel<<<dim3(B_, 4), 128>>>(conv2_w, conv2_b);
    conv3_kernel<<<dim3(B_, 4), 128>>>(conv3_w, conv3_b);
    gemm_input_kernel<<<dim3(G4_ / 128, (S_ * B_) / 128, 2), 256>>>(x, word_emb, w_ih_f, w_ih_b, b_f, b_b);
    zero_bar_kernel<<<1, 128>>>();
    lstm_persist_kernel<<<128, 256>>>(w_hh_f, w_hh_b, h0, c0);
    fc_kernel<<<S_, 256>>>(fc_w, fc_b);
    softmax_kernel<<<(B_ * L_ * 32 + 255) / 256, 256>>>();
    viterbi_kernel<<<B_, 32>>>(x, start_t, trans, end_t, out);
}

// round 15
// speedup vs baseline: 2.0934x; 2.0934x over previous
#include <cuda_runtime.h>
#include <cuda_bf16.h>
#include <math.h>

// ---------------- problem constants ----------------
#define B_   32
#define S_   128
#define E_   300
#define C_   100
#define EC_  50
#define LC_  50
#define H_   256
#define L_   17
#define G4_  1024          // 4*H
#define D_   400           // E + C

typedef unsigned long long u64;

// ---------------- scratch ----------------
__device__ float g_conv1[B_ * C_ * 48];
__device__ float g_conv2[B_ * C_ * 45];
__device__ float g_pooled[B_ * C_];
__device__ float g_gin[2 * S_ * G4_ * B_];              // preactivations [dir][s][r][b]  (TRANSPOSED)
__device__ float g_hseq[2 * S_ * B_ * H_];              // LSTM outputs [dir][s][b][256]
__device__ float g_em[B_ * L_ * S_];                    // emissions [b][l][s]
__device__ __align__(128) unsigned int g_ctrs[8 * 32];  // 8 arrival counters, one per 128B line

__device__ __forceinline__ float sigm(float x) { return 1.f / (1.f + expf(-x)); }

// packed f32x2 fma: acc += a*b (elementwise on 2 floats)
__device__ __forceinline__ void ffma2(u64 &acc, u64 a, u64 b) {
    asm("fma.rn.f32x2 %0, %1, %2, %0;" : "+l"(acc) : "l"(a), "l"(b));
}
// 128-bit shared load as two u64 (two f32x2 pairs)
__device__ __forceinline__ void lds_v2u64(u64 &a, u64 &b, const void* p) {
    unsigned sa = (unsigned)__cvta_generic_to_shared(p);
    asm volatile("ld.shared.v2.b64 {%0, %1}, [%2];" : "=l"(a), "=l"(b) : "r"(sa));
}
__device__ __forceinline__ float f2sum(u64 v) {
    float lo, hi;
    asm("mov.b64 {%0, %1}, %2;" : "=f"(lo), "=f"(hi) : "l"(v));
    return lo + hi;
}

// ---------------- char CNN ----------------
__global__ void __launch_bounds__(128) conv1_kernel(const int* __restrict__ xc,
                                                    const float* __restrict__ cemb,
                                                    const float* __restrict__ w1,
                                                    const float* __restrict__ b1) {
    int b = blockIdx.x;
    int oc0 = blockIdx.y * 25;
    __shared__ float ce[EC_][LC_];
    int tid = threadIdx.x;
    for (int i = tid; i < EC_ * LC_; i += 128) {
        int e = i / LC_, t = i % LC_;
        ce[e][t] = cemb[xc[b * LC_ + t] * EC_ + e];
    }
    __syncthreads();
    for (int i = tid; i < 25 * 48; i += 128) {
        int o = i / 48, t = i % 48;
        const float* wr = w1 + (size_t)(oc0 + o) * (EC_ * 3);
        float acc = b1[oc0 + o];
        for (int e = 0; e < EC_; e++) {
            acc += ce[e][t + 0] * wr[e * 3 + 0];
            acc += ce[e][t + 1] * wr[e * 3 + 1];
            acc += ce[e][t + 2] * wr[e * 3 + 2];
        }
        g_conv1[b * (C_ * 48) + (oc0 + o) * 48 + t] = fmaxf(acc, 0.f);
    }
}

__global__ void __launch_bounds__(128) conv2_kernel(const float* __restrict__ w2,
                                                    const float* __restrict__ b2) {
    int b = blockIdx.x;
    int oc0 = blockIdx.y * 25;
    __shared__ float in_s[C_][48];
    int tid = threadIdx.x;
    for (int i = tid; i < C_ * 48; i += 128) ((float*)in_s)[i] = g_conv1[b * (C_ * 48) + i];
    __syncthreads();
    for (int i = tid; i < 25 * 45; i += 128) {
        int o = i / 45, t = i % 45;
        const float* wr = w2 + (size_t)(oc0 + o) * (C_ * 4);
        float acc = b2[oc0 + o];
        for (int ic = 0; ic < C_; ic++) {
            acc += in_s[ic][t + 0] * wr[ic * 4 + 0];
            acc += in_s[ic][t + 1] * wr[ic * 4 + 1];
            acc += in_s[ic][t + 2] * wr[ic * 4 + 2];
            acc += in_s[ic][t + 3] * wr[ic * 4 + 3];
        }
        g_conv2[b * (C_ * 45) + (oc0 + o) * 45 + t] = fmaxf(acc, 0.f);
    }
}

__global__ void __launch_bounds__(128) conv3_kernel(const float* __restrict__ w3,
                                                    const float* __restrict__ b3) {
    int b = blockIdx.x;
    int oc0 = blockIdx.y * 25;
    __shared__ float in_s[C_][45];
    __shared__ float out_s[25][41];
    int tid = threadIdx.x;
    for (int i = tid; i < C_ * 45; i += 128) ((float*)in_s)[i] = g_conv2[b * (C_ * 45) + i];
    __syncthreads();
    for (int i = tid; i < 25 * 41; i += 128) {
        int o = i / 41, t = i % 41;
        const float* wr = w3 + (size_t)(oc0 + o) * (C_ * 5);
        float acc = b3[oc0 + o];
        for (int ic = 0; ic < C_; ic++) {
            acc += in_s[ic][t + 0] * wr[ic * 5 + 0];
            acc += in_s[ic][t + 1] * wr[ic * 5 + 1];
            acc += in_s[ic][t + 2] * wr[ic * 5 + 2];
            acc += in_s[ic][t + 3] * wr[ic * 5 + 3];
            acc += in_s[ic][t + 4] * wr[ic * 5 + 4];
        }
        out_s[o][t] = fmaxf(acc, 0.f);
    }
    __syncthreads();
    if (tid < 25) {
        float m = out_s[tid][0];
        for (int t = 1; t < 41; t++) m = fmaxf(m, out_s[tid][t]);
        g_pooled[b * C_ + oc0 + tid] = m;
    }
}

// ---------------- input GEMM (K=400), single-buffered (best measured) ----------------
__global__ void __launch_bounds__(256) gemm_input_kernel(const int* __restrict__ x,
                                                         const float* __restrict__ word_emb,
                                                         const float* __restrict__ w_ih_f,
                                                         const float* __restrict__ w_ih_b,
                                                         const float* __restrict__ b_f,
                                                         const float* __restrict__ b_b) {
    const int dir = blockIdx.z;
    const float* __restrict__ W = dir ? w_ih_b : w_ih_f;
    const float* __restrict__ bias = dir ? b_b : b_f;
    float* __restrict__ out = g_gin + (size_t)dir * (S_ * G4_ * B_);
    const int m0 = blockIdx.y * 128;
    const int n0 = blockIdx.x * 128;
    __shared__ float As[16][132];
    __shared__ float Bs[16][132];
    __shared__ int wid[128];
    __shared__ float bsh[128];
    const int tid = threadIdx.x;
    if (tid < 128) {
        int m = m0 + tid;
        wid[tid] = x[(m & 31) * S_ + (m >> 5)];   // b = m&31, s = m>>5
        bsh[tid] = bias[n0 + tid];
    }
    __syncthreads();
    const int tx = tid & 15, ty = tid >> 4;
    float acc[8][8];
    #pragma unroll
    for (int i = 0; i < 8; i++)
        #pragma unroll
        for (int j = 0; j < 8; j++) acc[i][j] = 0.f;

    for (int k0 = 0; k0 < 400; k0 += 16) {
        #pragma unroll
        for (int l = 0; l < 2; l++) {
            int idx = tid + l * 256;
            int row = idx >> 2;
            int kq = (idx & 3) * 4;
            int k = k0 + kq;
            float4 av;
            if (k < 300) {
                av = *reinterpret_cast<const float4*>(word_emb + (size_t)wid[row] * E_ + k);
            } else {
                int bb = (m0 + row) & 31;
                av = *reinterpret_cast<const float4*>(g_pooled + bb * C_ + (k - 300));
            }
            As[kq + 0][row] = av.x;
            As[kq + 1][row] = av.y;
            As[kq + 2][row] = av.z;
            As[kq + 3][row] = av.w;
            float4 bv = *reinterpret_cast<const float4*>(W + (size_t)(n0 + row) * D_ + k);
            Bs[kq + 0][row] = bv.x;
            Bs[kq + 1][row] = bv.y;
            Bs[kq + 2][row] = bv.z;
            Bs[kq + 3][row] = bv.w;
        }
        __syncthreads();
        #pragma unroll
        for (int kk = 0; kk < 16; kk++) {
            float a[8], bq[8];
            #pragma unroll
            for (int i = 0; i < 8; i++) a[i] = As[kk][ty * 8 + i];
            #pragma unroll
            for (int j = 0; j < 8; j++) bq[j] = Bs[kk][tx * 8 + j];
            #pragma unroll
            for (int i = 0; i < 8; i++)
                #pragma unroll
                for (int j = 0; j < 8; j++) acc[i][j] += a[i] * bq[j];
        }
        __syncthreads();
    }
    #pragma unroll
    for (int i = 0; i < 8; i++) {
        int m = m0 + ty * 8 + i;
        int s = m >> 5;
        int bb = m & 31;
        float* obase = out + (size_t)s * (G4_ * B_) + bb;
        #pragma unroll
        for (int j = 0; j < 8; j++) {
            int n = n0 + tx * 8 + j;
            obase[(size_t)n * B_] = acc[i][j] + bsh[tx * 8 + j];
        }
    }
}

// ---------------- persistent bidirectional LSTM ----------------
__global__ void __launch_bounds__(8) zero_bar_kernel() { g_ctrs[threadIdx.x * 32] = 0u; }

// Split-counter per-direction barrier:
//   arrival: red.release to counter (dir*4 + blk&3), 16 arrivals each -> 4x less
//            LTS atomic serialization than a single per-direction counter.
//   detect : threads 0..3 acquire-poll one counter each; syncthreads publishes.
__device__ __forceinline__ void dir_barrier(int dir, int blk, int t) {
    __syncthreads();
    const unsigned tgt = 16u * (unsigned)(t + 1);
    if (threadIdx.x == 0) {
        asm volatile("red.release.gpu.global.add.u32 [%0], 1;"
                     :: "l"(&g_ctrs[(dir * 4 + (blk & 3)) * 32]) : "memory");
    }
    if (threadIdx.x < 4) {
        unsigned v;
        const unsigned int* ctr = &g_ctrs[(dir * 4 + threadIdx.x) * 32];
        do {
            asm volatile("ld.acquire.gpu.global.u32 %0, [%1];"
                         : "=r"(v) : "l"(ctr) : "memory");
        } while (v < tgt);
    }
    __syncthreads();
}

// 128 blocks (64/dir), 256 thr. Warp = K-eighth, covers ALL 16 gate rows.
__global__ void __launch_bounds__(256) lstm_persist_kernel(const float* __restrict__ w_hh_f,
                                                           const float* __restrict__ w_hh_b,
                                                           const float* __restrict__ h0,
                                                           const float* __restrict__ c0) {
    const int dir = blockIdx.x >> 6;
    const int blk = blockIdx.x & 63;
    const int j0 = blk * 4;                // 4 hidden units per block
    const float* __restrict__ W = dir ? w_hh_b : w_hh_f;
    __shared__ __align__(16) float wsh[16][256];   // [rr = gate*4+unit][k]
    __shared__ __align__(16) float hs[32][260];    // [b][k], +4 pad -> conflict-free LDS.128
    __shared__ float psh[8][16][33];               // K-eighth partials [kh][rr][b]
    __shared__ float csh[4][32];                   // cell state [u][b]
    const int tid = threadIdx.x;
    for (int i = tid; i < 16 * 256; i += 256) {
        int r = i >> 8, k = i & 255;
        int row = (r >> 2) * H_ + j0 + (r & 3);
        wsh[r][k] = W[(size_t)row * H_ + k];
    }
    if (tid < 128) {
        int u = tid >> 5, b = tid & 31;
        csh[u][b] = c0[dir * (B_ * H_) + b * H_ + j0 + u];
    }
    __syncthreads();

    float* __restrict__ hseq = g_hseq + (size_t)dir * (S_ * B_ * H_);
    const float* __restrict__ gin = g_gin + (size_t)dir * (S_ * G4_ * B_);
    const int wd = tid >> 5;               // warp 0..7 = K-eighth
    const int lane = tid & 31;             // batch
    const int kbase = wd * 32;             // 32 k per eighth (8 chunks of 4)
    const int cu = tid >> 5;               // combine role: unit (valid when tid<128)

    for (int t = 0; t < S_; t++) {
        const int s = dir ? (S_ - 1 - t) : t;
        const int sp = dir ? (s + 1) : (s - 1);
        const float* hprev = (t == 0) ? (h0 + dir * (B_ * H_))
                                      : (hseq + (size_t)sp * (B_ * H_));
        // prefetch gin for the combine stage (independent of h)
        const float* grow = gin + (size_t)s * (G4_ * B_);
        float gpre0 = 0.f, gpre1 = 0.f, gpre2 = 0.f, gpre3 = 0.f;
        if (tid < 128) {
            gpre0 = __ldg(&grow[(0 * H_ + j0 + cu) * B_ + lane]);
            gpre1 = __ldg(&grow[(1 * H_ + j0 + cu) * B_ + lane]);
            gpre2 = __ldg(&grow[(2 * H_ + j0 + cu) * B_ + lane]);
            gpre3 = __ldg(&grow[(3 * H_ + j0 + cu) * B_ + lane]);
        }
        // stage h -> smem (coherent: written by other blocks intra-kernel)
        const float4* hp4 = (const float4*)hprev;
        #pragma unroll
        for (int i = 0; i < 8; i++) {
            int idx = tid + i * 256;
            int b = idx >> 6, kq = idx & 63;
            float4 v = __ldcg(&hp4[idx]);
            *(float4*)&hs[b][kq * 4] = v;
        }
        __syncthreads();

        // all 16 rows x K-eighth partial dot; h loaded ONCE per chunk
        u64 acc[16];
        #pragma unroll
        for (int r = 0; r < 16; r++) acc[r] = 0;
        #pragma unroll
        for (int c = 0; c < 8; c++) {
            u64 h01, h23;
            lds_v2u64(h01, h23, &hs[lane][kbase + c * 4]);
            #pragma unroll
            for (int r = 0; r < 16; r++) {
                u64 w01, w23;
                lds_v2u64(w01, w23, &wsh[r][kbase + c * 4]);   // warp broadcast
                ffma2(acc[r], w01, h01);
                ffma2(acc[r], w23, h23);
            }
        }
        #pragma unroll
        for (int r = 0; r < 16; r++) psh[wd][r][lane] = f2sum(acc[r]);
        __syncthreads();

        if (tid < 128) {
            int u = cu, b = lane;
            float gi = gpre0, gf = gpre1, gg = gpre2, go = gpre3;
            #pragma unroll
            for (int kh = 0; kh < 8; kh++) {
                gi += psh[kh][0 * 4 + u][b];
                gf += psh[kh][1 * 4 + u][b];
                gg += psh[kh][2 * 4 + u][b];
                go += psh[kh][3 * 4 + u][b];
            }
            float c = sigm(gf) * csh[u][b] + sigm(gi) * tanhf(gg);
            csh[u][b] = c;
            __stcg(&hseq[(size_t)s * (B_ * H_) + b * H_ + j0 + u], sigm(go) * tanhf(c));
        }
        dir_barrier(dir, blk, t);
    }
}

// ---------------- fc -> emission logits (layout [b][l][s]) ----------------
__global__ void __launch_bounds__(256) fc_kernel(const float* __restrict__ fc_w,
                                                 const float* __restrict__ fc_b) {
    const int s = blockIdx.x;
    __shared__ float ws[L_ * 512];
    const int tid = threadIdx.x;
    for (int i = tid; i < L_ * 512; i += 256) ws[i] = fc_w[i];
    __syncthreads();
    const float* hf = g_hseq + (size_t)s * (B_ * H_);
    const float* hb = g_hseq + (size_t)(S_ * B_ * H_) + (size_t)s * (B_ * H_);
    for (int idx = tid; idx < B_ * L_; idx += 256) {
        int b = idx / L_, l = idx % L_;
        const float4* hf4 = (const float4*)(hf + b * H_);
        const float4* hb4 = (const float4*)(hb + b * H_);
        const float4* w0 = (const float4*)(ws + l * 512);
        const float4* w1 = w0 + 64;
        float acc = fc_b[l];
        #pragma unroll 8
        for (int k = 0; k < 64; k++) {
            float4 h4 = hf4[k], w4 = w0[k];
            acc += h4.x * w4.x + h4.y * w4.y + h4.z * w4.z + h4.w * w4.w;
            float4 h5 = hb4[k], w5 = w1[k];
            acc += h5.x * w5.x + h5.y * w5.y + h5.z * w5.z + h5.w * w5.w;
        }
        g_em[b * (L_ * S_) + l * S_ + s] = acc;
    }
}

// ---------------- softmax over seq dim ----------------
__global__ void __launch_bounds__(256) softmax_kernel() {
    int w = (blockIdx.x * 256 + threadIdx.x) >> 5;
    int lane = threadIdx.x & 31;
    if (w >= B_ * L_) return;
    float* row = g_em + (size_t)w * S_;
    float v[4];
    float mx = -1e30f;
    #pragma unroll
    for (int q = 0; q < 4; q++) { v[q] = row[lane + 32 * q]; mx = fmaxf(mx, v[q]); }
    #pragma unroll
    for (int o = 16; o; o >>= 1) mx = fmaxf(mx, __shfl_xor_sync(0xffffffffu, mx, o));
    float sum = 0.f;
    #pragma unroll
    for (int q = 0; q < 4; q++) { v[q] = expf(v[q] - mx); sum += v[q]; }
    #pragma unroll
    for (int o = 16; o; o >>= 1) sum += __shfl_xor_sync(0xffffffffu, sum, o);
    #pragma unroll
    for (int q = 0; q < 4; q++) row[lane + 32 * q] = v[q] / sum;
}

// ---------------- Viterbi: one warp-block per batch; float output ----------------
__global__ void __launch_bounds__(32) viterbi_kernel(const int* __restrict__ x,
                                                     const float* __restrict__ start_t,
                                                     const float* __restrict__ trans,
                                                     const float* __restrict__ end_t,
                                                     float* __restrict__ out) {
    const int b = blockIdx.x;
    const int j = threadIdx.x;
    __shared__ float esh[S_ * L_];         // [s][l]
    __shared__ float tsh[L_ * L_];
    __shared__ int hist[(S_ - 1) * L_];
    __shared__ unsigned char msk[S_];
    for (int i = j; i < S_ * L_; i += 32) {
        int l = i >> 7, s = i & 127;
        esh[s * L_ + l] = g_em[b * (L_ * S_) + i];
    }
    for (int i = j; i < L_ * L_; i += 32) tsh[i] = trans[i];
    for (int s = j; s < S_; s += 32) msk[s] = (x[b * S_ + s] != 0) ? 1 : 0;
    __syncthreads();
    const int jj = (j < L_) ? j : 0;
    float score = (j < L_) ? (start_t[j] + esh[jj]) : -1e30f;
    for (int s = 1; s < S_; s++) {
        float e = esh[s * L_ + jj];
        float best = -1e30f;
        int arg = 0;
        for (int i = 0; i < L_; i++) {
            float si = __shfl_sync(0xffffffffu, score, i);
            float v = si + tsh[i * L_ + jj];
            if (v > best) { best = v; arg = i; }
        }
        if (j < L_) {
            hist[(s - 1) * L_ + j] = arg;
            if (msk[s]) score = best + e;
        }
    }
    if (j < L_) score += end_t[j];
    float best = -1e30f;
    int last = 0;
    for (int i = 0; i < L_; i++) {
        float si = __shfl_sync(0xffffffffu, score, i);
        if (si > best) { best = si; last = i; }
    }
    if (j == 0) {
        int cur = last;
        out[b * S_ + S_ - 1] = (float)cur;
        for (int s = S_ - 2; s >= 0; s--) {
            if (msk[s + 1]) cur = hist[s * L_ + cur];
            out[b * S_ + s] = (float)cur;
        }
    }
}

// ---------------- launch ----------------
extern "C" void kernel_launch(void* const* d_in, const int* in_sizes, int n_in,
                              void* d_out, int out_size) {
    const int*   x        = (const int*)d_in[0];
    const int*   x_char   = (const int*)d_in[1];
    const float* word_emb = (const float*)d_in[2];
    const float* char_emb = (const float*)d_in[3];
    const float* conv1_w  = (const float*)d_in[4];
    const float* conv1_b  = (const float*)d_in[5];
    const float* conv2_w  = (const float*)d_in[6];
    const float* conv2_b  = (const float*)d_in[7];
    const float* conv3_w  = (const float*)d_in[8];
    const float* conv3_b  = (const float*)d_in[9];
    const float* w_ih_f   = (const float*)d_in[10];
    const float* w_hh_f   = (const float*)d_in[11];
    const float* b_f      = (const float*)d_in[12];
    const float* w_ih_b   = (const float*)d_in[13];
    const float* w_hh_b   = (const float*)d_in[14];
    const float* b_b      = (const float*)d_in[15];
    const float* h0       = (const float*)d_in[16];
    const float* c0       = (const float*)d_in[17];
    const float* fc_w     = (const float*)d_in[18];
    const float* fc_b     = (const float*)d_in[19];
    const float* start_t  = (const float*)d_in[20];
    const float* trans    = (const float*)d_in[21];
    const float* end_t    = (const float*)d_in[22];
    float* out = (float*)d_out;

    conv1_kernel<<<dim3(B_, 4), 128>>>(x_char, char_emb, conv1_w, conv1_b);
    conv2_kernel<<<dim3(B_, 4), 128>>>(conv2_w, conv2_b);
    conv3_kernel<<<dim3(B_, 4), 128>>>(conv3_w, conv3_b);
    gemm_input_kernel<<<dim3(G4_ / 128, (S_ * B_) / 128, 2), 256>>>(x, word_emb, w_ih_f, w_ih_b, b_f, b_b);
    zero_bar_kernel<<<1, 8>>>();
    lstm_persist_kernel<<<128, 256>>>(w_hh_f, w_hh_b, h0, c0);
    fc_kernel<<<S_, 256>>>(fc_w, fc_b);
    softmax_kernel<<<(B_ * L_ * 32 + 255) / 256, 256>>>();
    viterbi_kernel<<<B_, 32>>>(x, start_t, trans, end_t, out);
}

// round 16
// speedup vs baseline: 2.1774x; 1.0401x over previous
#include <cuda_runtime.h>
#include <cuda_bf16.h>
#include <math.h>

// ---------------- problem constants ----------------
#define B_   32
#define S_   128
#define E_   300
#define C_   100
#define EC_  50
#define LC_  50
#define H_   256
#define L_   17
#define G4_  1024          // 4*H
#define D_   400           // E + C

typedef unsigned long long u64;

// ---------------- scratch ----------------
__device__ float g_conv1[B_ * C_ * 48];
__device__ float g_conv2[B_ * C_ * 45];
__device__ float g_pooled[B_ * C_];
__device__ float g_gin[2 * S_ * G4_ * B_];              // preactivations [dir][s][r][b]  (TRANSPOSED)
__device__ float g_hseq[2 * S_ * B_ * H_];              // LSTM outputs [dir][s][b][256]
__device__ float g_em[B_ * L_ * S_];                    // emissions [b][l][s]
__device__ __align__(128) unsigned int g_barf;          // fwd arrival counter
__device__ __align__(128) unsigned int g_barb;          // bwd arrival counter

__device__ __forceinline__ float sigm(float x) { return 1.f / (1.f + expf(-x)); }

// packed f32x2 fma: acc += a*b (elementwise on 2 floats; fp32 rounding per lane)
__device__ __forceinline__ void ffma2(u64 &acc, u64 a, u64 b) {
    asm("fma.rn.f32x2 %0, %1, %2, %0;" : "+l"(acc) : "l"(a), "l"(b));
}
// 128-bit shared load as two u64 (two f32x2 pairs)
__device__ __forceinline__ void lds_v2u64(u64 &a, u64 &b, const void* p) {
    unsigned sa = (unsigned)__cvta_generic_to_shared(p);
    asm volatile("ld.shared.v2.b64 {%0, %1}, [%2];" : "=l"(a), "=l"(b) : "r"(sa));
}
__device__ __forceinline__ float f2sum(u64 v) {
    float lo, hi;
    asm("mov.b64 {%0, %1}, %2;" : "=f"(lo), "=f"(hi) : "l"(v));
    return lo + hi;
}
__device__ __forceinline__ void f2unpack(u64 v, float &lo, float &hi) {
    asm("mov.b64 {%0, %1}, %2;" : "=f"(lo), "=f"(hi) : "l"(v));
}
__device__ __forceinline__ u64 f2dup(float x) {
    u64 r;
    asm("mov.b64 %0, {%1, %1};" : "=l"(r) : "f"(x));
    return r;
}

// ---------------- char CNN ----------------
__global__ void __launch_bounds__(128) conv1_kernel(const int* __restrict__ xc,
                                                    const float* __restrict__ cemb,
                                                    const float* __restrict__ w1,
                                                    const float* __restrict__ b1) {
    int b = blockIdx.x;
    int oc0 = blockIdx.y * 25;
    __shared__ float ce[EC_][LC_];
    int tid = threadIdx.x;
    for (int i = tid; i < EC_ * LC_; i += 128) {
        int e = i / LC_, t = i % LC_;
        ce[e][t] = cemb[xc[b * LC_ + t] * EC_ + e];
    }
    __syncthreads();
    for (int i = tid; i < 25 * 48; i += 128) {
        int o = i / 48, t = i % 48;
        const float* wr = w1 + (size_t)(oc0 + o) * (EC_ * 3);
        float acc = b1[oc0 + o];
        for (int e = 0; e < EC_; e++) {
            acc += ce[e][t + 0] * wr[e * 3 + 0];
            acc += ce[e][t + 1] * wr[e * 3 + 1];
            acc += ce[e][t + 2] * wr[e * 3 + 2];
        }
        g_conv1[b * (C_ * 48) + (oc0 + o) * 48 + t] = fmaxf(acc, 0.f);
    }
}

__global__ void __launch_bounds__(128) conv2_kernel(const float* __restrict__ w2,
                                                    const float* __restrict__ b2) {
    int b = blockIdx.x;
    int oc0 = blockIdx.y * 25;
    __shared__ float in_s[C_][48];
    int tid = threadIdx.x;
    for (int i = tid; i < C_ * 48; i += 128) ((float*)in_s)[i] = g_conv1[b * (C_ * 48) + i];
    __syncthreads();
    for (int i = tid; i < 25 * 45; i += 128) {
        int o = i / 45, t = i % 45;
        const float* wr = w2 + (size_t)(oc0 + o) * (C_ * 4);
        float acc = b2[oc0 + o];
        for (int ic = 0; ic < C_; ic++) {
            acc += in_s[ic][t + 0] * wr[ic * 4 + 0];
            acc += in_s[ic][t + 1] * wr[ic * 4 + 1];
            acc += in_s[ic][t + 2] * wr[ic * 4 + 2];
            acc += in_s[ic][t + 3] * wr[ic * 4 + 3];
        }
        g_conv2[b * (C_ * 45) + (oc0 + o) * 45 + t] = fmaxf(acc, 0.f);
    }
}

__global__ void __launch_bounds__(128) conv3_kernel(const float* __restrict__ w3,
                                                    const float* __restrict__ b3) {
    int b = blockIdx.x;
    int oc0 = blockIdx.y * 25;
    __shared__ float in_s[C_][45];
    __shared__ float out_s[25][41];
    int tid = threadIdx.x;
    for (int i = tid; i < C_ * 45; i += 128) ((float*)in_s)[i] = g_conv2[b * (C_ * 45) + i];
    __syncthreads();
    for (int i = tid; i < 25 * 41; i += 128) {
        int o = i / 41, t = i % 41;
        const float* wr = w3 + (size_t)(oc0 + o) * (C_ * 5);
        float acc = b3[oc0 + o];
        for (int ic = 0; ic < C_; ic++) {
            acc += in_s[ic][t + 0] * wr[ic * 5 + 0];
            acc += in_s[ic][t + 1] * wr[ic * 5 + 1];
            acc += in_s[ic][t + 2] * wr[ic * 5 + 2];
            acc += in_s[ic][t + 3] * wr[ic * 5 + 3];
            acc += in_s[ic][t + 4] * wr[ic * 5 + 4];
        }
        out_s[o][t] = fmaxf(acc, 0.f);
    }
    __syncthreads();
    if (tid < 25) {
        float m = out_s[tid][0];
        for (int t = 1; t < 41; t++) m = fmaxf(m, out_s[tid][t]);
        g_pooled[b * C_ + oc0 + tid] = m;
    }
}

// ---------------- input GEMM (K=400), single-buffered, f32x2-packed core ----------------
__global__ void __launch_bounds__(256) gemm_input_kernel(const int* __restrict__ x,
                                                         const float* __restrict__ word_emb,
                                                         const float* __restrict__ w_ih_f,
                                                         const float* __restrict__ w_ih_b,
                                                         const float* __restrict__ b_f,
                                                         const float* __restrict__ b_b) {
    const int dir = blockIdx.z;
    const float* __restrict__ W = dir ? w_ih_b : w_ih_f;
    const float* __restrict__ bias = dir ? b_b : b_f;
    float* __restrict__ out = g_gin + (size_t)dir * (S_ * G4_ * B_);
    const int m0 = blockIdx.y * 128;
    const int n0 = blockIdx.x * 128;
    __shared__ __align__(16) float As[16][132];
    __shared__ __align__(16) float Bs[16][132];
    __shared__ int wid[128];
    __shared__ float bsh[128];
    const int tid = threadIdx.x;
    if (tid < 128) {
        int m = m0 + tid;
        wid[tid] = x[(m & 31) * S_ + (m >> 5)];   // b = m&31, s = m>>5
        bsh[tid] = bias[n0 + tid];
    }
    __syncthreads();
    const int tx = tid & 15, ty = tid >> 4;
    u64 acc2[4][8];                        // i-pairs x j; each u64 = rows (2i2, 2i2+1)
    #pragma unroll
    for (int i = 0; i < 4; i++)
        #pragma unroll
        for (int j = 0; j < 8; j++) acc2[i][j] = 0;

    for (int k0 = 0; k0 < 400; k0 += 16) {
        #pragma unroll
        for (int l = 0; l < 2; l++) {
            int idx = tid + l * 256;
            int row = idx >> 2;
            int kq = (idx & 3) * 4;
            int k = k0 + kq;
            float4 av;
            if (k < 300) {
                av = *reinterpret_cast<const float4*>(word_emb + (size_t)wid[row] * E_ + k);
            } else {
                int bb = (m0 + row) & 31;
                av = *reinterpret_cast<const float4*>(g_pooled + bb * C_ + (k - 300));
            }
            As[kq + 0][row] = av.x;
            As[kq + 1][row] = av.y;
            As[kq + 2][row] = av.z;
            As[kq + 3][row] = av.w;
            float4 bv = *reinterpret_cast<const float4*>(W + (size_t)(n0 + row) * D_ + k);
            Bs[kq + 0][row] = bv.x;
            Bs[kq + 1][row] = bv.y;
            Bs[kq + 2][row] = bv.z;
            Bs[kq + 3][row] = bv.w;
        }
        __syncthreads();
        #pragma unroll
        for (int kk = 0; kk < 16; kk++) {
            u64 a01, a23, a45, a67;
            lds_v2u64(a01, a23, &As[kk][ty * 8]);
            lds_v2u64(a45, a67, &As[kk][ty * 8 + 4]);
            float4 b0 = *(const float4*)&Bs[kk][tx * 8];
            float4 b1 = *(const float4*)&Bs[kk][tx * 8 + 4];
            float bq[8] = {b0.x, b0.y, b0.z, b0.w, b1.x, b1.y, b1.z, b1.w};
            #pragma unroll
            for (int j = 0; j < 8; j++) {
                u64 bd = f2dup(bq[j]);
                ffma2(acc2[0][j], a01, bd);
                ffma2(acc2[1][j], a23, bd);
                ffma2(acc2[2][j], a45, bd);
                ffma2(acc2[3][j], a67, bd);
            }
        }
        __syncthreads();
    }
    #pragma unroll
    for (int i2 = 0; i2 < 4; i2++) {
        #pragma unroll
        for (int half = 0; half < 2; half++) {
            int m = m0 + ty * 8 + i2 * 2 + half;
            int s = m >> 5;
            int bb = m & 31;
            float* obase = out + (size_t)s * (G4_ * B_) + bb;
            #pragma unroll
            for (int j = 0; j < 8; j++) {
                float lo, hi;
                f2unpack(acc2[i2][j], lo, hi);
                float v = half ? hi : lo;
                int n = n0 + tx * 8 + j;
                obase[(size_t)n * B_] = v + bsh[tx * 8 + j];
            }
        }
    }
}

// ---------------- persistent bidirectional LSTM (round-13 proven config) ----------------
__global__ void zero_bar_kernel() { g_barf = 0u; g_barb = 0u; }

__device__ __forceinline__ void grid_barrier(unsigned int* ctr, unsigned int target) {
    __syncthreads();
    if (threadIdx.x == 0) {
        asm volatile("red.release.gpu.global.add.u32 [%0], 1;"
                     :: "l"(ctr) : "memory");
        unsigned int v;
        do {
            asm volatile("ld.acquire.gpu.global.u32 %0, [%1];"
                         : "=r"(v) : "l"(ctr) : "memory");
        } while (v < target);
    }
    __syncthreads();
}

// 128 blocks (64/dir), 256 thr. Warp = K-eighth, covers ALL 16 gate rows.
__global__ void __launch_bounds__(256) lstm_persist_kernel(const float* __restrict__ w_hh_f,
                                                           const float* __restrict__ w_hh_b,
                                                           const float* __restrict__ h0,
                                                           const float* __restrict__ c0) {
    const int dir = blockIdx.x >> 6;
    const int blk = blockIdx.x & 63;
    const int j0 = blk * 4;                // 4 hidden units per block
    const float* __restrict__ W = dir ? w_hh_b : w_hh_f;
    __shared__ __align__(16) float wsh[16][256];   // [rr = gate*4+unit][k]
    __shared__ __align__(16) float hs[32][260];    // [b][k], +4 pad -> conflict-free LDS.128
    __shared__ float psh[8][16][33];               // K-eighth partials [kh][rr][b]
    __shared__ float csh[4][32];                   // cell state [u][b]
    const int tid = threadIdx.x;
    for (int i = tid; i < 16 * 256; i += 256) {
        int r = i >> 8, k = i & 255;
        int row = (r >> 2) * H_ + j0 + (r & 3);
        wsh[r][k] = W[(size_t)row * H_ + k];
    }
    if (tid < 128) {
        int u = tid >> 5, b = tid & 31;
        csh[u][b] = c0[dir * (B_ * H_) + b * H_ + j0 + u];
    }
    __syncthreads();

    float* __restrict__ hseq = g_hseq + (size_t)dir * (S_ * B_ * H_);
    const float* __restrict__ gin = g_gin + (size_t)dir * (S_ * G4_ * B_);
    unsigned int* ctr = dir ? &g_barb : &g_barf;
    const int wd = tid >> 5;               // warp 0..7 = K-eighth
    const int lane = tid & 31;             // batch
    const int kbase = wd * 32;             // 32 k per eighth (8 chunks of 4)
    const int cu = tid >> 5;               // combine role: unit (valid when tid<128)

    for (int t = 0; t < S_; t++) {
        const int s = dir ? (S_ - 1 - t) : t;
        const int sp = dir ? (s + 1) : (s - 1);
        const float* hprev = (t == 0) ? (h0 + dir * (B_ * H_))
                                      : (hseq + (size_t)sp * (B_ * H_));
        // prefetch gin for the combine stage (independent of h)
        const float* grow = gin + (size_t)s * (G4_ * B_);
        float gpre0 = 0.f, gpre1 = 0.f, gpre2 = 0.f, gpre3 = 0.f;
        if (tid < 128) {
            gpre0 = __ldg(&grow[(0 * H_ + j0 + cu) * B_ + lane]);
            gpre1 = __ldg(&grow[(1 * H_ + j0 + cu) * B_ + lane]);
            gpre2 = __ldg(&grow[(2 * H_ + j0 + cu) * B_ + lane]);
            gpre3 = __ldg(&grow[(3 * H_ + j0 + cu) * B_ + lane]);
        }
        // stage h -> smem (coherent: written by other blocks intra-kernel)
        const float4* hp4 = (const float4*)hprev;
        #pragma unroll
        for (int i = 0; i < 8; i++) {
            int idx = tid + i * 256;
            int b = idx >> 6, kq = idx & 63;
            float4 v = __ldcg(&hp4[idx]);
            *(float4*)&hs[b][kq * 4] = v;
        }
        __syncthreads();

        // all 16 rows x K-eighth partial dot; h loaded ONCE per chunk
        u64 acc[16];
        #pragma unroll
        for (int r = 0; r < 16; r++) acc[r] = 0;
        #pragma unroll
        for (int c = 0; c < 8; c++) {
            u64 h01, h23;
            lds_v2u64(h01, h23, &hs[lane][kbase + c * 4]);
            #pragma unroll
            for (int r = 0; r < 16; r++) {
                u64 w01, w23;
                lds_v2u64(w01, w23, &wsh[r][kbase + c * 4]);   // warp broadcast
                ffma2(acc[r], w01, h01);
                ffma2(acc[r], w23, h23);
            }
        }
        #pragma unroll
        for (int r = 0; r < 16; r++) psh[wd][r][lane] = f2sum(acc[r]);
        __syncthreads();

        if (tid < 128) {
            int u = cu, b = lane;
            float gi = gpre0, gf = gpre1, gg = gpre2, go = gpre3;
            #pragma unroll
            for (int kh = 0; kh < 8; kh++) {
                gi += psh[kh][0 * 4 + u][b];
                gf += psh[kh][1 * 4 + u][b];
                gg += psh[kh][2 * 4 + u][b];
                go += psh[kh][3 * 4 + u][b];
            }
            float c = sigm(gf) * csh[u][b] + sigm(gi) * tanhf(gg);
            csh[u][b] = c;
            __stcg(&hseq[(size_t)s * (B_ * H_) + b * H_ + j0 + u], sigm(go) * tanhf(c));
        }
        grid_barrier(ctr, 64u * (unsigned)(t + 1));
    }
}

// ---------------- fc -> emission logits (layout [b][l][s]) ----------------
__global__ void __launch_bounds__(256) fc_kernel(const float* __restrict__ fc_w,
                                                 const float* __restrict__ fc_b) {
    const int s = blockIdx.x;
    __shared__ float ws[L_ * 512];
    const int tid = threadIdx.x;
    for (int i = tid; i < L_ * 512; i += 256) ws[i] = fc_w[i];
    __syncthreads();
    const float* hf = g_hseq + (size_t)s * (B_ * H_);
    const float* hb = g_hseq + (size_t)(S_ * B_ * H_) + (size_t)s * (B_ * H_);
    for (int idx = tid; idx < B_ * L_; idx += 256) {
        int b = idx / L_, l = idx % L_;
        const float4* hf4 = (const float4*)(hf + b * H_);
        const float4* hb4 = (const float4*)(hb + b * H_);
        const float4* w0 = (const float4*)(ws + l * 512);
        const float4* w1 = w0 + 64;
        float acc = fc_b[l];
        #pragma unroll 8
        for (int k = 0; k < 64; k++) {
            float4 h4 = hf4[k], w4 = w0[k];
            acc += h4.x * w4.x + h4.y * w4.y + h4.z * w4.z + h4.w * w4.w;
            float4 h5 = hb4[k], w5 = w1[k];
            acc += h5.x * w5.x + h5.y * w5.y + h5.z * w5.z + h5.w * w5.w;
        }
        g_em[b * (L_ * S_) + l * S_ + s] = acc;
    }
}

// ---------------- softmax over seq dim ----------------
__global__ void __launch_bounds__(256) softmax_kernel() {
    int w = (blockIdx.x * 256 + threadIdx.x) >> 5;
    int lane = threadIdx.x & 31;
    if (w >= B_ * L_) return;
    float* row = g_em + (size_t)w * S_;
    float v[4];
    float mx = -1e30f;
    #pragma unroll
    for (int q = 0; q < 4; q++) { v[q] = row[lane + 32 * q]; mx = fmaxf(mx, v[q]); }
    #pragma unroll
    for (int o = 16; o; o >>= 1) mx = fmaxf(mx, __shfl_xor_sync(0xffffffffu, mx, o));
    float sum = 0.f;
    #pragma unroll
    for (int q = 0; q < 4; q++) { v[q] = expf(v[q] - mx); sum += v[q]; }
    #pragma unroll
    for (int o = 16; o; o >>= 1) sum += __shfl_xor_sync(0xffffffffu, sum, o);
    #pragma unroll
    for (int q = 0; q < 4; q++) row[lane + 32 * q] = v[q] / sum;
}

// ---------------- Viterbi: one warp-block per batch; float output ----------------
__global__ void __launch_bounds__(32) viterbi_kernel(const int* __restrict__ x,
                                                     const float* __restrict__ start_t,
                                                     const float* __restrict__ trans,
                                                     const float* __restrict__ end_t,
                                                     float* __restrict__ out) {
    const int b = blockIdx.x;
    const int j = threadIdx.x;
    __shared__ float esh[S_ * L_];         // [s][l]
    __shared__ float tsh[L_ * L_];
    __shared__ int hist[(S_ - 1) * L_];
    __shared__ unsigned char msk[S_];
    for (int i = j; i < S_ * L_; i += 32) {
        int l = i >> 7, s = i & 127;
        esh[s * L_ + l] = g_em[b * (L_ * S_) + i];
    }
    for (int i = j; i < L_ * L_; i += 32) tsh[i] = trans[i];
    for (int s = j; s < S_; s += 32) msk[s] = (x[b * S_ + s] != 0) ? 1 : 0;
    __syncthreads();
    const int jj = (j < L_) ? j : 0;
    float score = (j < L_) ? (start_t[j] + esh[jj]) : -1e30f;
    for (int s = 1; s < S_; s++) {
        float e = esh[s * L_ + jj];
        float best = -1e30f;
        int arg = 0;
        for (int i = 0; i < L_; i++) {
            float si = __shfl_sync(0xffffffffu, score, i);
            float v = si + tsh[i * L_ + jj];
            if (v > best) { best = v; arg = i; }
        }
        if (j < L_) {
            hist[(s - 1) * L_ + j] = arg;
            if (msk[s]) score = best + e;
        }
    }
    if (j < L_) score += end_t[j];
    float best = -1e30f;
    int last = 0;
    for (int i = 0; i < L_; i++) {
        float si = __shfl_sync(0xffffffffu, score, i);
        if (si > best) { best = si; last = i; }
    }
    if (j == 0) {
        int cur = last;
        out[b * S_ + S_ - 1] = (float)cur;
        for (int s = S_ - 2; s >= 0; s--) {
            if (msk[s + 1]) cur = hist[s * L_ + cur];
            out[b * S_ + s] = (float)cur;
        }
    }
}

// ---------------- launch ----------------
extern "C" void kernel_launch(void* const* d_in, const int* in_sizes, int n_in,
                              void* d_out, int out_size) {
    const int*   x        = (const int*)d_in[0];
    const int*   x_char   = (const int*)d_in[1];
    const float* word_emb = (const float*)d_in[2];
    const float* char_emb = (const float*)d_in[3];
    const float* conv1_w  = (const float*)d_in[4];
    const float* conv1_b  = (const float*)d_in[5];
    const float* conv2_w  = (const float*)d_in[6];
    const float* conv2_b  = (const float*)d_in[7];
    const float* conv3_w  = (const float*)d_in[8];
    const float* conv3_b  = (const float*)d_in[9];
    const float* w_ih_f   = (const float*)d_in[10];
    const float* w_hh_f   = (const float*)d_in[11];
    const float* b_f      = (const float*)d_in[12];
    const float* w_ih_b   = (const float*)d_in[13];
    const float* w_hh_b   = (const float*)d_in[14];
    const float* b_b      = (const float*)d_in[15];
    const float* h0       = (const float*)d_in[16];
    const float* c0       = (const float*)d_in[17];
    const float* fc_w     = (const float*)d_in[18];
    const float* fc_b     = (const float*)d_in[19];
    const float* start_t  = (const float*)d_in[20];
    const float* trans    = (const float*)d_in[21];
    const float* end_t    = (const float*)d_in[22];
    float* out = (float*)d_out;

    conv1_kernel<<<dim3(B_, 4), 128>>>(x_char, char_emb, conv1_w, conv1_b);
    conv2_kernel<<<dim3(B_, 4), 128>>>(conv2_w, conv2_b);
    conv3_kernel<<<dim3(B_, 4), 128>>>(conv3_w, conv3_b);
    gemm_input_kernel<<<dim3(G4_ / 128, (S_ * B_) / 128, 2), 256>>>(x, word_emb, w_ih_f, w_ih_b, b_f, b_b);
    zero_bar_kernel<<<1, 1>>>();
    lstm_persist_kernel<<<128, 256>>>(w_hh_f, w_hh_b, h0, c0);
    fc_kernel<<<S_, 256>>>(fc_w, fc_b);
    softmax_kernel<<<(B_ * L_ * 32 + 255) / 256, 256>>>();
    viterbi_kernel<<<B_, 32>>>(x, start_t, trans, end_t, out);
}